// round 10
// baseline (speedup 1.0000x reference)
#include <cuda_runtime.h>

// Micromagnetic LLG RK4 solver — Round 10: R9's neighbor-only per-step sync
// (double-buffered global state, monotonic padded flags) COMBINED with R8's
// 4-layer thread mapping for 32 warps/SM.
// 128 CTAs x 1024 threads; CTA r owns global rows {2r, 2r+1}; 10-row window
// (4-row halo each side). Thread (ty = tid>>8 in 0..3, c = tid&255) handles
// window rows L = ty + 4k (k=0..2): exactly 5 valid row-computes per thread
// per RK4 step (validity L in [s, 9-s], warp-uniform). Layers ty<2 own the
// real rows (window row 4+ty = global 2r+ty). One neighbor sync per step:
// publish own flag, poll CTAs r-2..r+2; step n writes g_mbuf[n&1].

#define NXg 256
#define NYg 256
#define PLANE (NXg * NYg)
#define TSTEPS 256
#define NSIG 2
#define NSRC 3
#define NPROBE 5
#define RELAXN 100
#define NBLK 128
#define NT 1024
#define NROWS 10
#define SROW 258
#define SMEM_BYTES (2 * NROWS * SROW * 16)

__device__ float4 g_mbuf[2][PLANE];
__device__ unsigned g_flag[NBLK * 8];    // zero-init; one flag per 32B sector

// Publish own flag (release) then wait for the 4 dependency CTAs (proven R9).
#define NBRSYNC()                                                              \
  { seq++;                                                                     \
    const unsigned tgt = fbase + seq;                                          \
    __syncthreads();                                                           \
    if (threadIdx.x == 0) {                                                    \
        __threadfence();                                                       \
        asm volatile("st.global.cg.u32 [%0], %1;"                              \
                     :: "l"(g_flag + 8 * r), "r"(tgt) : "memory");             \
        unsigned fa, fb, fc, fd;                                               \
        do {                                                                   \
            asm volatile("ld.global.cg.u32 %0, [%1];"                          \
                         : "=r"(fa) : "l"(g_flag + fn0) : "memory");           \
            asm volatile("ld.global.cg.u32 %0, [%1];"                          \
                         : "=r"(fb) : "l"(g_flag + fn1) : "memory");           \
            asm volatile("ld.global.cg.u32 %0, [%1];"                          \
                         : "=r"(fc) : "l"(g_flag + fn2) : "memory");           \
            asm volatile("ld.global.cg.u32 %0, [%1];"                          \
                         : "=r"(fd) : "l"(g_flag + fn3) : "memory");           \
        } while (((int)(fa - tgt) | (int)(fb - tgt) |                          \
                  (int)(fc - tgt) | (int)(fd - tgt)) < 0);                     \
        __threadfence();                                                       \
    }                                                                          \
    __syncthreads(); }

__device__ __forceinline__ float3 lap_torque(
    float ux, float uy, float uz,
    float sx, float sy, float sz,          // N+S+W+E sums
    float bx, float by, float bz_, float bzAdd,
    float CEx, float CD, float alpha, float inv)
{
    float lx = sx - 4.0f * ux, ly = sy - 4.0f * uy, lz = sz - 4.0f * uz;
    float Bx = bx + CEx * lx;
    float By = by + CEx * ly;
    float Bz = bz_ + bzAdd + CEx * lz - CD * uz;
    float c1x = uy * Bz - uz * By;
    float c1y = uz * Bx - ux * Bz;
    float c1z = ux * By - uy * Bx;
    float c2x = uy * c1z - uz * c1y;
    float c2y = uz * c1x - ux * c1z;
    float c2z = ux * c1y - uy * c1x;
    const float CS = 1.0e-4f;
    float3 t;
    t.x = -inv * (c1x + alpha * c2x) + CS * (ux * uy);
    t.y = -inv * (c1y + alpha * c2y) + CS * (-(uz * uz + ux * ux));
    t.z = -inv * (c1z + alpha * c2z) + CS * (uy * uz);
    return t;
}

#define U(b, L) (smf4 + ((b) * NROWS + (L)) * SROW)

// One RK4 stage (R8 mapping): rows L = ty + 4k, valid iff L in [s, 9-s].
#define STAGE(s, ib, ob, coefE, wK, LAST)                                      \
  {                                                                            \
    _Pragma("unroll")                                                          \
    for (int k = 0; k < 3; k++) {                                              \
      int L = ty + 4 * k;                                                      \
      if (L >= (s) && L <= 9 - (s)) {                                          \
        float4 nN = U(ib, L - 1)[c + 1];                                       \
        float4 nS = U(ib, L + 1)[c + 1];                                       \
        float4 nW = U(ib, L)[c];                                               \
        float4 nE = U(ib, L)[c + 2];                                           \
        float3 kv = lap_torque(ux[k], uy[k], uz[k],                            \
            nN.x + nS.x + nW.x + nE.x,                                         \
            nN.y + nS.y + nW.y + nE.y,                                         \
            nN.z + nS.z + nW.z + nE.z,                                         \
            bxr[k], byr[k], bzr[k], bzadd[k], CEx, CD, alpha, inv);            \
        if (own && k == 1) { ax += (wK) * kv.x; ay += (wK) * kv.y;             \
                             az += (wK) * kv.z; }                              \
        if (!(LAST)) {                                                         \
          float nx2 = mxr[k] + (coefE) * kv.x;                                 \
          float ny2 = myr[k] + (coefE) * kv.y;                                 \
          float nz2 = mzr[k] + (coefE) * kv.z;                                 \
          ux[k] = nx2; uy[k] = ny2; uz[k] = nz2;                               \
          float4 ov = make_float4(nx2, ny2, nz2, 0.0f);                        \
          U(ob, L)[c + 1] = ov;                                                \
          if (c == 0)   U(ob, L)[0]   = ov;                                    \
          if (c == 255) U(ob, L)[257] = ov;                                    \
        }                                                                      \
      }                                                                        \
    }                                                                          \
    if (!(LAST)) __syncthreads();                                              \
  }

#define RK4STEP()                                                              \
  { float ax = 0.0f, ay = 0.0f, az = 0.0f;                                     \
    STAGE(1, 0, 1, h2, 1.0f, false)                                            \
    STAGE(2, 1, 0, h2, 2.0f, false)                                            \
    STAGE(3, 0, 1, hh, 2.0f, false)                                            \
    STAGE(4, 1, 0, 0.0f, 1.0f, true)                                           \
    if (own) { mxr[1] += h6 * ax; myr[1] += h6 * ay; mzr[1] += h6 * az; } }

// Refresh window from buffer `gb` after a sync: own row (own && k==1) from
// registers, other handled rows from global. Repopulate smem buffer 0.
#define RELOAD(gb)                                                             \
  { _Pragma("unroll")                                                          \
    for (int k = 0; k < 3; k++) {                                              \
      int L = ty + 4 * k;                                                      \
      if (L <= 9) {                                                            \
        float4 v;                                                              \
        if (own && k == 1) v = make_float4(mxr[1], myr[1], mzr[1], 0.0f);      \
        else               v = __ldcg(&(gb)[growr[k] * NYg + c]);              \
        mxr[k] = v.x; myr[k] = v.y; mzr[k] = v.z;                              \
        ux[k] = v.x; uy[k] = v.y; uz[k] = v.z;                                 \
        U(0, L)[c + 1] = v;                                                    \
        if (c == 0)   U(0, L)[0]   = v;                                        \
        if (c == 255) U(0, L)[257] = v;                                        \
      }                                                                        \
    }                                                                          \
    __syncthreads(); }

__global__ void __launch_bounds__(NT, 1)
mm_kernel(const float* __restrict__ sig, const float* __restrict__ Bext,
          const float* __restrict__ MsatP, const int* __restrict__ srcP,
          const int* __restrict__ probeP, const int* __restrict__ finalP,
          float* __restrict__ out)
{
    extern __shared__ float4 smf4[];

    const int tid  = threadIdx.x;
    const int c    = tid & 255;
    const int ty   = tid >> 8;              // 0..3, warp-uniform
    const int r    = blockIdx.x;
    const bool own = (ty < 2);              // layers 0/1 own a real row
    const int gown = 2 * r + ty;            // global row when own

    // Neighbor flag offsets (clamped at edges; clamped entries trivially
    // satisfied since all flags advance uniformly).
    const int fn0 = 8 * (r - 2 < 0 ? 0 : r - 2);
    const int fn1 = 8 * (r - 1 < 0 ? 0 : r - 1);
    const int fn2 = 8 * (r + 1 > NBLK - 1 ? NBLK - 1 : r + 1);
    const int fn3 = 8 * (r + 2 > NBLK - 1 ? NBLK - 1 : r + 2);
    const unsigned fbase = g_flag[8 * r];   // race-free: only CTA r writes it
    unsigned seq = 0;

    const float Msat = *MsatP;
    const float CEx = (float)(2.0 * 3.5e-12 / ((double)Msat * (5e-8 * 5e-8)));
    const float CD  = (float)(4e-7 * 3.14159265358979323846 * (double)Msat);
    const float hh  = (float)(175950000000.0 * 5e-12);   // GAMMA_LL * DT
    const float h2  = 0.5f * hh;
    const float h6  = hh * (1.0f / 6.0f);
    const int final_board = *finalP;

    // Window row L = ty + 4k -> global grow[k] = clamp(2r - 4 + L).
    int growr[3];
    #pragma unroll
    for (int k = 0; k < 3; k++) {
        int g = 2 * r - 4 + ty + 4 * k;
        growr[k] = g < 0 ? 0 : (g > NXg - 1 ? NXg - 1 : g);
    }

    // B_ext per handled row -> registers.
    float bxr[3], byr[3], bzr[3];
    #pragma unroll
    for (int k = 0; k < 3; k++) {
        int gi = growr[k] * NYg + c;
        bxr[k] = __ldg(Bext + 0 * PLANE + gi);
        byr[k] = __ldg(Bext + 1 * PLANE + gi);
        bzr[k] = __ldg(Bext + 2 * PLANE + gi);
    }

    // Source-id per handled row.
    int sid[3];
    {
        int s0r = srcP[0], s0c = srcP[1];
        int s1r = srcP[2], s1c = srcP[3];
        int s2r = srcP[4], s2c = srcP[5];
        #pragma unroll
        for (int k = 0; k < 3; k++) {
            int g = growr[k];
            sid[k] = (g == s0r && c == s0c) ? 0 :
                     (g == s1r && c == s1c) ? 1 :
                     (g == s2r && c == s2c) ? 2 : -1;
        }
    }
    // Probe-id at owned cell.
    int pid = -1;
    if (own) {
        #pragma unroll
        for (int k = 0; k < NPROBE; k++)
            if (probeP[2 * k] == gown && probeP[2 * k + 1] == c) pid = k;
    }

    float ux[3], uy[3], uz[3];           // stage-input values
    float mxr[3], myr[3], mzr[3];        // base m for this step
    float bzadd[3];
    #pragma unroll
    for (int k = 0; k < 3; k++) bzadd[k] = 0.0f;

    // ---- init: m0 = (0,1,0) everywhere ----
    #pragma unroll
    for (int k = 0; k < 3; k++) {
        int L = ty + 4 * k;
        mxr[k] = 0.0f; myr[k] = 1.0f; mzr[k] = 0.0f;
        ux[k] = 0.0f;  uy[k] = 1.0f;  uz[k] = 0.0f;
        if (L <= 9) {
            float4 v = make_float4(0.0f, 1.0f, 0.0f, 0.0f);
            U(0, L)[c + 1] = v;
            if (c == 0)   U(0, L)[0]   = v;
            if (c == 255) U(0, L)[257] = v;
        }
    }
    __syncthreads();

    // ---- relax phase: alpha = 0.5 ----
    {
        const float alpha = 0.5f;
        const float inv = 1.0f / (1.0f + alpha * alpha);
        for (int s = 0; s < RELAXN; s++) {
            RK4STEP();
            if (own)
                __stcg(&g_mbuf[(seq + 1) & 1][gown * NYg + c],
                       make_float4(mxr[1], myr[1], mzr[1], 0.0f));
            NBRSYNC();
            RELOAD(g_mbuf[seq & 1]);
        }
    }
    const float mrx = mxr[1], mry = myr[1], mrz = mzr[1];   // m_relaxed (own)

    // ---- driven phase: alpha = 0.01 ----
    {
        const float alpha = 0.01f;
        const float inv = 1.0f / (1.0f + alpha * alpha);
        for (int sgn = 0; sgn < NSIG; sgn++) {
            if (sgn > 0) {   // reset to m_relaxed (a publish event)
                if (own) {
                    mxr[1] = mrx; myr[1] = mry; mzr[1] = mrz;
                    __stcg(&g_mbuf[(seq + 1) & 1][gown * NYg + c],
                           make_float4(mrx, mry, mrz, 0.0f));
                }
                NBRSYNC();
                RELOAD(g_mbuf[seq & 1]);
            }
            for (int t = 0; t < TSTEPS; t++) {
                const float* sp = sig + (sgn * TSTEPS + t) * NSRC;
                float sv0 = __ldg(sp + 0), sv1 = __ldg(sp + 1), sv2 = __ldg(sp + 2);
                #pragma unroll
                for (int k = 0; k < 3; k++)
                    bzadd[k] = (sid[k] == 0) ? sv0 :
                               (sid[k] == 1) ? sv1 :
                               (sid[k] == 2) ? sv2 : 0.0f;
                RK4STEP();
                if (own)
                    __stcg(&g_mbuf[(seq + 1) & 1][gown * NYg + c],
                           make_float4(mxr[1], myr[1], mzr[1], 0.0f));
                if (pid >= 0) {
                    float val = final_board ? (mzr[1] - mrz) * Msat : mzr[1];
                    out[(sgn * TSTEPS + t) * NPROBE + pid] = val;
                }
                NBRSYNC();
                RELOAD(g_mbuf[seq & 1]);
            }
        }
    }
}

extern "C" void kernel_launch(void* const* d_in, const int* in_sizes, int n_in,
                              void* d_out, int out_size) {
    const float* sig    = (const float*)d_in[0];  // (2, 256, 3)
    const float* Bext   = (const float*)d_in[1];  // (1, 3, 256, 256)
    const float* MsatP  = (const float*)d_in[2];  // scalar
    const int*   srcP   = (const int*)d_in[3];    // (3, 2)
    const int*   probeP = (const int*)d_in[4];    // (5, 2)
    const int*   finalP = (const int*)d_in[5];    // scalar
    float* out = (float*)d_out;                   // (2, 256, 5)
    (void)in_sizes; (void)n_in; (void)out_size;

    cudaFuncSetAttribute(mm_kernel,
                         cudaFuncAttributeMaxDynamicSharedMemorySize,
                         SMEM_BYTES);
    mm_kernel<<<NBLK, NT, SMEM_BYTES>>>(sig, Bext, MsatP, srcP, probeP,
                                        finalP, out);
}

// round 11
// speedup vs baseline: 1.0463x; 1.0463x over previous
#include <cuda_runtime.h>

// Micromagnetic LLG RK4 solver — Round 11: TWO-PHASE halo-2 stepping.
// 128 CTAs x 512 threads; CTA r owns global rows {2r, 2r+1}; thread
// (ty = tid>>8, c = tid&255) owns cell (2r+ty, c).
// Each RK4 step is split: phase 1 = stages 1-2 on a 6-row window (halo 2),
// publish u2 (stage-2 value) -> neighbor sync; phase 2 = stages 3-4,
// publish m -> neighbor sync. Row-computes per thread per step: 6 (vs 10
// for halo-4), smem traffic -40%, and halo deps shrink to CTAs r+-1 only.
// Thread handles window rows L = ty + 2k (k=0..2); own cell at k==1
// (L = 2+ty). N/S neighbors via smem window rows; W/E via clamped in-row
// indices (no halo-column stores). Sync = R9's proven monotonic-flag
// publish + poll (2 flags). u2: single global buffer (WAR-safe: 2 flag
// levels between overwrite and neighbors' last read); m: double-buffered.

#define NXg 256
#define NYg 256
#define PLANE (NXg * NYg)
#define TSTEPS 256
#define NSIG 2
#define NSRC 3
#define NPROBE 5
#define RELAXN 100
#define NBLK 128
#define NT 512
#define SROW 258
#define SMEM_BYTES (3 * 6 * SROW * 16)

__device__ float4 g_mbuf[2][PLANE];
__device__ float4 g_u2[PLANE];
__device__ unsigned g_flag[NBLK * 8];   // zero-init; 1 flag / 32B sector

// Publish own flag (release) then wait for the 2 dependency CTAs (r-1, r+1).
#define NBRSYNC()                                                              \
  { seq++;                                                                     \
    const unsigned tgt = fbase + seq;                                          \
    __syncthreads();                                                           \
    if (threadIdx.x == 0) {                                                    \
        __threadfence();                                                       \
        asm volatile("st.global.cg.u32 [%0], %1;"                              \
                     :: "l"(g_flag + 8 * r), "r"(tgt) : "memory");             \
        unsigned fa, fb;                                                       \
        do {                                                                   \
            asm volatile("ld.global.cg.u32 %0, [%1];"                          \
                         : "=r"(fa) : "l"(g_flag + fnA) : "memory");           \
            asm volatile("ld.global.cg.u32 %0, [%1];"                          \
                         : "=r"(fb) : "l"(g_flag + fnB) : "memory");           \
        } while (((int)(fa - tgt) | (int)(fb - tgt)) < 0);                     \
        __threadfence();                                                       \
    }                                                                          \
    __syncthreads(); }

__device__ __forceinline__ float3 lap_torque(
    float ux, float uy, float uz,
    float sx, float sy, float sz,          // N+S+W+E sums
    float bx, float by, float bz_,         // bz_ already includes source
    float CEx, float CD, float alpha, float inv)
{
    float lx = sx - 4.0f * ux, ly = sy - 4.0f * uy, lz = sz - 4.0f * uz;
    float Bx = bx + CEx * lx;
    float By = by + CEx * ly;
    float Bz = bz_ + CEx * lz - CD * uz;
    float c1x = uy * Bz - uz * By;
    float c1y = uz * Bx - ux * Bz;
    float c1z = ux * By - uy * Bx;
    float c2x = uy * c1z - uz * c1y;
    float c2y = uz * c1x - ux * c1z;
    float c2z = ux * c1y - uy * c1x;
    const float CS = 1.0e-4f;
    float3 t;
    t.x = -inv * (c1x + alpha * c2x) + CS * (ux * uy);
    t.y = -inv * (c1y + alpha * c2y) + CS * (-(uz * uz + ux * ux));
    t.z = -inv * (c1z + alpha * c2z) + CS * (uy * uz);
    return t;
}

#define U(b, L) (smf4 + ((b) * 6 + (L)) * SROW)
#define MB 0
#define AB 1
#define BB 2

// Torque at window row L of buffer b, center value ux[k] (registers).
#define TORQ(b, L, k, kv)                                                      \
  { const float4* rN = U(b, (L) - 1);                                          \
    const float4* rS = U(b, (L) + 1);                                          \
    const float4* r0 = U(b, (L));                                              \
    float4 nN = rN[c + 1], nS = rS[c + 1], nW = r0[wOff], nE = r0[eOff];       \
    kv = lap_torque(ux[k], uy[k], uz[k],                                       \
        nN.x + nS.x + nW.x + nE.x,                                             \
        nN.y + nS.y + nW.y + nE.y,                                             \
        nN.z + nS.z + nW.z + nE.z,                                             \
        bxr[k], byr[k], bzall[k], CEx, CD, alpha, inv); }

// One full RK4 step (two phases, two neighbor syncs).
#define RK4STEP()                                                              \
  { float ax, ay, az;                                                          \
    /* stage 1: bufM -> bufA, rows 1..4 */                                     \
    _Pragma("unroll")                                                          \
    for (int k = 0; k < 3; k++) {                                              \
      int L = ty + 2 * k;                                                      \
      if (L >= 1 && L <= 4) {                                                  \
        float3 kv; TORQ(MB, L, k, kv);                                         \
        if (k == 1) { ax = kv.x; ay = kv.y; az = kv.z; }                       \
        float nx2 = mxr[k] + h2 * kv.x;                                        \
        float ny2 = myr[k] + h2 * kv.y;                                        \
        float nz2 = mzr[k] + h2 * kv.z;                                        \
        ux[k] = nx2; uy[k] = ny2; uz[k] = nz2;                                 \
        U(AB, L)[c + 1] = make_float4(nx2, ny2, nz2, 0.0f);                    \
      }                                                                        \
    }                                                                          \
    __syncthreads();                                                           \
    /* stage 2 (own row): bufA -> u2, publish */                               \
    { int L = 2 + ty;                                                          \
      float3 kv; TORQ(AB, L, 1, kv);                                           \
      ax += 2.0f * kv.x; ay += 2.0f * kv.y; az += 2.0f * kv.z;                 \
      float nx2 = mxr[1] + h2 * kv.x;                                          \
      float ny2 = myr[1] + h2 * kv.y;                                          \
      float nz2 = mzr[1] + h2 * kv.z;                                          \
      ux[1] = nx2; uy[1] = ny2; uz[1] = nz2;                                   \
      float4 u2v = make_float4(nx2, ny2, nz2, 0.0f);                           \
      U(BB, L)[c + 1] = u2v;                                                   \
      __stcg(&g_u2[gcown], u2v); }                                             \
    NBRSYNC();                                                                 \
    /* reload u2 halo rows into bufB + regs */                                 \
    _Pragma("unroll")                                                          \
    for (int k = 0; k < 3; k += 2) {                                           \
      int L = ty + 2 * k;                                                      \
      float4 v = __ldcg(&g_u2[goff[k]]);                                       \
      ux[k] = v.x; uy[k] = v.y; uz[k] = v.z;                                   \
      U(BB, L)[c + 1] = v;                                                     \
    }                                                                          \
    __syncthreads();                                                           \
    /* stage 3: bufB -> bufA, rows 1..4 */                                     \
    _Pragma("unroll")                                                          \
    for (int k = 0; k < 3; k++) {                                              \
      int L = ty + 2 * k;                                                      \
      if (L >= 1 && L <= 4) {                                                  \
        float3 kv; TORQ(BB, L, k, kv);                                         \
        if (k == 1) { ax += 2.0f * kv.x; ay += 2.0f * kv.y;                    \
                      az += 2.0f * kv.z; }                                     \
        float nx2 = mxr[k] + hh * kv.x;                                        \
        float ny2 = myr[k] + hh * kv.y;                                        \
        float nz2 = mzr[k] + hh * kv.z;                                        \
        ux[k] = nx2; uy[k] = ny2; uz[k] = nz2;                                 \
        U(AB, L)[c + 1] = make_float4(nx2, ny2, nz2, 0.0f);                    \
      }                                                                        \
    }                                                                          \
    __syncthreads();                                                           \
    /* stage 4 (own row) + final combine */                                    \
    { int L = 2 + ty;                                                          \
      float3 kv; TORQ(AB, L, 1, kv);                                           \
      ax += kv.x; ay += kv.y; az += kv.z;                                      \
      mxr[1] += h6 * ax; myr[1] += h6 * ay; mzr[1] += h6 * az; } }

// Publish m (to buffer mp^1), sync, reload window m from that buffer.
#define PUBLISH_RELOAD_M()                                                     \
  { mp ^= 1;                                                                   \
    __stcg(&g_mbuf[mp][gcown], make_float4(mxr[1], myr[1], mzr[1], 0.0f));     \
    NBRSYNC();                                                                 \
    _Pragma("unroll")                                                          \
    for (int k = 0; k < 3; k++) {                                              \
      int L = ty + 2 * k;                                                      \
      float4 v;                                                                \
      if (k == 1) v = make_float4(mxr[1], myr[1], mzr[1], 0.0f);               \
      else        v = __ldcg(&g_mbuf[mp][goff[k]]);                            \
      mxr[k] = v.x; myr[k] = v.y; mzr[k] = v.z;                                \
      ux[k] = v.x; uy[k] = v.y; uz[k] = v.z;                                   \
      U(MB, L)[c + 1] = v;                                                     \
    }                                                                          \
    __syncthreads(); }

__global__ void __launch_bounds__(NT, 1)
mm_kernel(const float* __restrict__ sig, const float* __restrict__ Bext,
          const float* __restrict__ MsatP, const int* __restrict__ srcP,
          const int* __restrict__ probeP, const int* __restrict__ finalP,
          float* __restrict__ out)
{
    extern __shared__ float4 smf4[];

    const int tid  = threadIdx.x;
    const int c    = tid & 255;
    const int ty   = tid >> 8;              // 0/1, warp-uniform
    const int r    = blockIdx.x;
    const int gown = 2 * r + ty;            // owned global row
    const int gcown = gown * NYg + c;       // owned global cell index

    // Clamped in-row W/E smem indices (center at c+1).
    const int wOff = (c == 0) ? 1 : c;
    const int eOff = (c == 255) ? 256 : c + 2;

    // Neighbor flags: only r-1 / r+1 (halo-2 deps). Edge clamps to self.
    const int fnA = 8 * (r - 1 < 0 ? 0 : r - 1);
    const int fnB = 8 * (r + 1 > NBLK - 1 ? NBLK - 1 : r + 1);
    const unsigned fbase = g_flag[8 * r];   // race-free: only CTA r writes it
    unsigned seq = 0;
    int mp = 0;                             // current m buffer parity

    const float Msat = *MsatP;
    const float CEx = (float)(2.0 * 3.5e-12 / ((double)Msat * (5e-8 * 5e-8)));
    const float CD  = (float)(4e-7 * 3.14159265358979323846 * (double)Msat);
    const float hh  = (float)(175950000000.0 * 5e-12);   // GAMMA_LL * DT
    const float h2  = 0.5f * hh;
    const float h6  = hh * (1.0f / 6.0f);
    const int final_board = *finalP;

    // Window row L = ty + 2k -> global grow[k] = clamp(2r - 2 + L).
    int goff[3];
    int growr[3];
    #pragma unroll
    for (int k = 0; k < 3; k++) {
        int g = 2 * r - 2 + ty + 2 * k;
        growr[k] = g < 0 ? 0 : (g > NXg - 1 ? NXg - 1 : g);
        goff[k] = growr[k] * NYg + c;
    }

    // B_ext per handled row -> registers.
    float bxr[3], byr[3], bzr[3];
    #pragma unroll
    for (int k = 0; k < 3; k++) {
        bxr[k] = __ldg(Bext + 0 * PLANE + goff[k]);
        byr[k] = __ldg(Bext + 1 * PLANE + goff[k]);
        bzr[k] = __ldg(Bext + 2 * PLANE + goff[k]);
    }

    // Source-id per handled row.
    int sid[3];
    {
        int s0r = srcP[0], s0c = srcP[1];
        int s1r = srcP[2], s1c = srcP[3];
        int s2r = srcP[4], s2c = srcP[5];
        #pragma unroll
        for (int k = 0; k < 3; k++) {
            int g = growr[k];
            sid[k] = (g == s0r && c == s0c) ? 0 :
                     (g == s1r && c == s1c) ? 1 :
                     (g == s2r && c == s2c) ? 2 : -1;
        }
    }
    // Probe-id at owned cell.
    int pid = -1;
    #pragma unroll
    for (int k = 0; k < NPROBE; k++)
        if (probeP[2 * k] == gown && probeP[2 * k + 1] == c) pid = k;

    float ux[3], uy[3], uz[3];           // stage-input values
    float mxr[3], myr[3], mzr[3];        // m at handled rows (step base)
    float bzall[3];                      // bz + source for this step

    // ---- init: m0 = (0,1,0) everywhere ----
    #pragma unroll
    for (int k = 0; k < 3; k++) {
        int L = ty + 2 * k;
        mxr[k] = 0.0f; myr[k] = 1.0f; mzr[k] = 0.0f;
        ux[k] = 0.0f;  uy[k] = 1.0f;  uz[k] = 0.0f;
        U(MB, L)[c + 1] = make_float4(0.0f, 1.0f, 0.0f, 0.0f);
    }
    __syncthreads();

    // ---- relax phase: alpha = 0.5, no source ----
    {
        const float alpha = 0.5f;
        const float inv = 1.0f / (1.0f + alpha * alpha);
        #pragma unroll
        for (int k = 0; k < 3; k++) bzall[k] = bzr[k];
        for (int s = 0; s < RELAXN; s++) {
            RK4STEP();
            PUBLISH_RELOAD_M();
        }
    }
    const float mrx = mxr[1], mry = myr[1], mrz = mzr[1];   // m_relaxed (own)

    // ---- driven phase: alpha = 0.01 ----
    {
        const float alpha = 0.01f;
        const float inv = 1.0f / (1.0f + alpha * alpha);
        for (int sgn = 0; sgn < NSIG; sgn++) {
            if (sgn > 0) {   // reset to m_relaxed (publish + reload event)
                mxr[1] = mrx; myr[1] = mry; mzr[1] = mrz;
                PUBLISH_RELOAD_M();
            }
            for (int t = 0; t < TSTEPS; t++) {
                const float* sp = sig + (sgn * TSTEPS + t) * NSRC;
                float sv0 = __ldg(sp + 0), sv1 = __ldg(sp + 1), sv2 = __ldg(sp + 2);
                #pragma unroll
                for (int k = 0; k < 3; k++)
                    bzall[k] = bzr[k] + ((sid[k] == 0) ? sv0 :
                                         (sid[k] == 1) ? sv1 :
                                         (sid[k] == 2) ? sv2 : 0.0f);
                RK4STEP();
                if (pid >= 0) {
                    float val = final_board ? (mzr[1] - mrz) * Msat : mzr[1];
                    out[(sgn * TSTEPS + t) * NPROBE + pid] = val;
                }
                PUBLISH_RELOAD_M();
            }
        }
    }
}

extern "C" void kernel_launch(void* const* d_in, const int* in_sizes, int n_in,
                              void* d_out, int out_size) {
    const float* sig    = (const float*)d_in[0];  // (2, 256, 3)
    const float* Bext   = (const float*)d_in[1];  // (1, 3, 256, 256)
    const float* MsatP  = (const float*)d_in[2];  // scalar
    const int*   srcP   = (const int*)d_in[3];    // (3, 2)
    const int*   probeP = (const int*)d_in[4];    // (5, 2)
    const int*   finalP = (const int*)d_in[5];    // scalar
    float* out = (float*)d_out;                   // (2, 256, 5)
    (void)in_sizes; (void)n_in; (void)out_size;

    cudaFuncSetAttribute(mm_kernel,
                         cudaFuncAttributeMaxDynamicSharedMemorySize,
                         SMEM_BYTES);
    mm_kernel<<<NBLK, NT, SMEM_BYTES>>>(sig, Bext, MsatP, srcP, probeP,
                                        finalP, out);
}

// round 12
// speedup vs baseline: 1.8149x; 1.7346x over previous
#include <cuda_runtime.h>

// Micromagnetic LLG RK4 solver — Round 12: TAG-IN-DATA neighbor sync.
// Two-phase halo-2 stepping (R11 compute path, rel_err 0.0), but the
// inter-CTA handshake is fused into the data: every published float4
// carries a monotonic sequence tag in .w (STG.128 = one 16B sector
// transaction -> payload+tag visible together). Each thread polls its own
// 2 halo cells with LDG.128.cg until w >= expected — the poll IS the
// reload. No threadfence, no flag array, no thread-0 relay.
// m: double-buffered by tag parity. u2: single buffer (writer's next u2
// publish is gated by the reader's interleaved m publish -> no WAR, no
// tag-skip). Tag bases persist per CTA in g_base across graph replays.

#define NXg 256
#define NYg 256
#define PLANE (NXg * NYg)
#define TSTEPS 256
#define NSIG 2
#define NSRC 3
#define NPROBE 5
#define RELAXN 100
#define NBLK 128
#define NT 512
#define SROW 258
#define SMEM_BYTES (3 * 6 * SROW * 16)

__device__ float4 g_mbuf[2][PLANE];
__device__ float4 g_u2[PLANE];
__device__ unsigned g_base[NBLK * 8];   // [8r]=m count, [8r+1]=u2 count

__device__ __forceinline__ float4 ldcg4(const float4* p) {
    float4 v;
    asm volatile("ld.global.cg.v4.f32 {%0,%1,%2,%3}, [%4];"
                 : "=f"(v.x), "=f"(v.y), "=f"(v.z), "=f"(v.w)
                 : "l"(p) : "memory");
    return v;
}
__device__ __forceinline__ void stcg4(float4* p, float4 v) {
    asm volatile("st.global.cg.v4.f32 [%0], {%1,%2,%3,%4};"
                 :: "l"(p), "f"(v.x), "f"(v.y), "f"(v.z), "f"(v.w)
                 : "memory");
}

// Poll two tagged cells until both carry tag >= TAG (wraparound-safe).
#define POLL2(P0, P2, TAG, V0, V2)                                             \
  { V0 = ldcg4(P0); V2 = ldcg4(P2);                                            \
    while (((int)(__float_as_int(V0.w) - (int)(TAG)) |                         \
            (int)(__float_as_int(V2.w) - (int)(TAG))) < 0) {                   \
        V0 = ldcg4(P0); V2 = ldcg4(P2);                                        \
    } }

__device__ __forceinline__ float3 lap_torque(
    float ux, float uy, float uz,
    float sx, float sy, float sz,          // N+S+W+E sums
    float bx, float by, float bz_,         // bz_ already includes source
    float CEx, float CD, float alpha, float inv)
{
    float lx = sx - 4.0f * ux, ly = sy - 4.0f * uy, lz = sz - 4.0f * uz;
    float Bx = bx + CEx * lx;
    float By = by + CEx * ly;
    float Bz = bz_ + CEx * lz - CD * uz;
    float c1x = uy * Bz - uz * By;
    float c1y = uz * Bx - ux * Bz;
    float c1z = ux * By - uy * Bx;
    float c2x = uy * c1z - uz * c1y;
    float c2y = uz * c1x - ux * c1z;
    float c2z = ux * c1y - uy * c1x;
    const float CS = 1.0e-4f;
    float3 t;
    t.x = -inv * (c1x + alpha * c2x) + CS * (ux * uy);
    t.y = -inv * (c1y + alpha * c2y) + CS * (-(uz * uz + ux * ux));
    t.z = -inv * (c1z + alpha * c2z) + CS * (uy * uz);
    return t;
}

#define U(b, L) (smf4 + ((b) * 6 + (L)) * SROW)
#define MB 0
#define AB 1
#define BB 2

// Torque at window row L of buffer b, center value ux[k] (registers).
#define TORQ(b, L, k, kv)                                                      \
  { const float4* rN = U(b, (L) - 1);                                          \
    const float4* rS = U(b, (L) + 1);                                          \
    const float4* r0 = U(b, (L));                                              \
    float4 nN = rN[c + 1], nS = rS[c + 1], nW = r0[wOff], nE = r0[eOff];       \
    kv = lap_torque(ux[k], uy[k], uz[k],                                       \
        nN.x + nS.x + nW.x + nE.x,                                             \
        nN.y + nS.y + nW.y + nE.y,                                             \
        nN.z + nS.z + nW.z + nE.z,                                             \
        bxr[k], byr[k], bzall[k], CEx, CD, alpha, inv); }

// Publish own m (tagged, parity buffer ms&1).
#define PUBLISH_M()                                                            \
  { ms++;                                                                      \
    stcg4(&g_mbuf[ms & 1u][gcown],                                             \
          make_float4(mxr[1], myr[1], mzr[1], __int_as_float((int)ms))); }

// Poll m halo cells (tag ms), fill regs + smem MB rows.
#define POLL_FILL_M()                                                          \
  { float4 v0, v2;                                                             \
    POLL2(&g_mbuf[ms & 1u][goff0], &g_mbuf[ms & 1u][goff2], ms, v0, v2);       \
    mxr[0] = v0.x; myr[0] = v0.y; mzr[0] = v0.z;                               \
    ux[0] = v0.x;  uy[0] = v0.y;  uz[0] = v0.z;                                \
    mxr[2] = v2.x; myr[2] = v2.y; mzr[2] = v2.z;                               \
    ux[2] = v2.x;  uy[2] = v2.y;  uz[2] = v2.z;                                \
    ux[1] = mxr[1]; uy[1] = myr[1]; uz[1] = mzr[1];                            \
    U(MB, ty)[c + 1]     = v0;                                                 \
    U(MB, 2 + ty)[c + 1] = make_float4(mxr[1], myr[1], mzr[1], 0.0f);          \
    U(MB, 4 + ty)[c + 1] = v2;                                                 \
    __syncthreads(); }

// One full RK4 step; ends with the m publish (earliest neighbor wake).
#define RK4STEP()                                                              \
  { float ax, ay, az;                                                          \
    /* stage 1: MB -> AB, rows 1..4 */                                         \
    _Pragma("unroll")                                                          \
    for (int k = 0; k < 3; k++) {                                              \
      int L = ty + 2 * k;                                                      \
      if (L >= 1 && L <= 4) {                                                  \
        float3 kv; TORQ(MB, L, k, kv);                                         \
        if (k == 1) { ax = kv.x; ay = kv.y; az = kv.z; }                       \
        float nx2 = mxr[k] + h2 * kv.x;                                        \
        float ny2 = myr[k] + h2 * kv.y;                                        \
        float nz2 = mzr[k] + h2 * kv.z;                                        \
        ux[k] = nx2; uy[k] = ny2; uz[k] = nz2;                                 \
        U(AB, L)[c + 1] = make_float4(nx2, ny2, nz2, 0.0f);                    \
      }                                                                        \
    }                                                                          \
    __syncthreads();                                                           \
    /* stage 2 (own row): AB -> u2, tagged publish + poll */                   \
    { int L = 2 + ty;                                                          \
      float3 kv; TORQ(AB, L, 1, kv);                                           \
      ax += 2.0f * kv.x; ay += 2.0f * kv.y; az += 2.0f * kv.z;                 \
      float nx2 = mxr[1] + h2 * kv.x;                                          \
      float ny2 = myr[1] + h2 * kv.y;                                          \
      float nz2 = mzr[1] + h2 * kv.z;                                          \
      ux[1] = nx2; uy[1] = ny2; uz[1] = nz2;                                   \
      us++;                                                                    \
      float4 u2v = make_float4(nx2, ny2, nz2, __int_as_float((int)us));        \
      U(BB, L)[c + 1] = u2v;                                                   \
      stcg4(&g_u2[gcown], u2v);                                                \
      float4 w0, w2;                                                           \
      POLL2(&g_u2[goff0], &g_u2[goff2], us, w0, w2);                           \
      ux[0] = w0.x; uy[0] = w0.y; uz[0] = w0.z;                                \
      ux[2] = w2.x; uy[2] = w2.y; uz[2] = w2.z;                                \
      U(BB, ty)[c + 1]     = w0;                                               \
      U(BB, 4 + ty)[c + 1] = w2; }                                             \
    __syncthreads();                                                           \
    /* stage 3: BB -> AB, rows 1..4 */                                         \
    _Pragma("unroll")                                                          \
    for (int k = 0; k < 3; k++) {                                              \
      int L = ty + 2 * k;                                                      \
      if (L >= 1 && L <= 4) {                                                  \
        float3 kv; TORQ(BB, L, k, kv);                                         \
        if (k == 1) { ax += 2.0f * kv.x; ay += 2.0f * kv.y;                    \
                      az += 2.0f * kv.z; }                                     \
        float nx2 = mxr[k] + hh * kv.x;                                        \
        float ny2 = myr[k] + hh * kv.y;                                        \
        float nz2 = mzr[k] + hh * kv.z;                                        \
        ux[k] = nx2; uy[k] = ny2; uz[k] = nz2;                                 \
        U(AB, L)[c + 1] = make_float4(nx2, ny2, nz2, 0.0f);                    \
      }                                                                        \
    }                                                                          \
    __syncthreads();                                                           \
    /* stage 4 (own row) + final combine + publish */                          \
    { int L = 2 + ty;                                                          \
      float3 kv; TORQ(AB, L, 1, kv);                                           \
      ax += kv.x; ay += kv.y; az += kv.z;                                      \
      mxr[1] += h6 * ax; myr[1] += h6 * ay; mzr[1] += h6 * az;                 \
      PUBLISH_M(); } }

__global__ void __launch_bounds__(NT, 1)
mm_kernel(const float* __restrict__ sig, const float* __restrict__ Bext,
          const float* __restrict__ MsatP, const int* __restrict__ srcP,
          const int* __restrict__ probeP, const int* __restrict__ finalP,
          float* __restrict__ out)
{
    extern __shared__ float4 smf4[];

    const int tid  = threadIdx.x;
    const int c    = tid & 255;
    const int ty   = tid >> 8;              // 0/1, warp-uniform
    const int r    = blockIdx.x;
    const int gown = 2 * r + ty;            // owned global row
    const int gcown = gown * NYg + c;       // owned global cell index

    // Clamped in-row W/E smem indices (center at c+1).
    const int wOff = (c == 0) ? 1 : c;
    const int eOff = (c == 255) ? 256 : c + 2;

    // Tag bases (own 32B sector; written only by this CTA at run end;
    // all CTAs have identical publish counts -> globally uniform).
    unsigned ms = g_base[8 * r];
    unsigned us = g_base[8 * r + 1];

    const float Msat = *MsatP;
    const float CEx = (float)(2.0 * 3.5e-12 / ((double)Msat * (5e-8 * 5e-8)));
    const float CD  = (float)(4e-7 * 3.14159265358979323846 * (double)Msat);
    const float hh  = (float)(175950000000.0 * 5e-12);   // GAMMA_LL * DT
    const float h2  = 0.5f * hh;
    const float h6  = hh * (1.0f / 6.0f);
    const int final_board = *finalP;

    // Window row L = ty + 2k -> global grow[k] = clamp(2r - 2 + L).
    int growr[3];
    int goffA[3];
    #pragma unroll
    for (int k = 0; k < 3; k++) {
        int g = 2 * r - 2 + ty + 2 * k;
        growr[k] = g < 0 ? 0 : (g > NXg - 1 ? NXg - 1 : g);
        goffA[k] = growr[k] * NYg + c;
    }
    const int goff0 = goffA[0], goff2 = goffA[2];

    // B_ext per handled row -> registers.
    float bxr[3], byr[3], bzr[3];
    #pragma unroll
    for (int k = 0; k < 3; k++) {
        bxr[k] = __ldg(Bext + 0 * PLANE + goffA[k]);
        byr[k] = __ldg(Bext + 1 * PLANE + goffA[k]);
        bzr[k] = __ldg(Bext + 2 * PLANE + goffA[k]);
    }

    // Source-id per handled row.
    int sid[3];
    {
        int s0r = srcP[0], s0c = srcP[1];
        int s1r = srcP[2], s1c = srcP[3];
        int s2r = srcP[4], s2c = srcP[5];
        #pragma unroll
        for (int k = 0; k < 3; k++) {
            int g = growr[k];
            sid[k] = (g == s0r && c == s0c) ? 0 :
                     (g == s1r && c == s1c) ? 1 :
                     (g == s2r && c == s2c) ? 2 : -1;
        }
    }
    // Probe-id at owned cell.
    int pid = -1;
    #pragma unroll
    for (int k = 0; k < NPROBE; k++)
        if (probeP[2 * k] == gown && probeP[2 * k + 1] == c) pid = k;

    float ux[3], uy[3], uz[3];           // stage-input values
    float mxr[3], myr[3], mzr[3];        // m at handled rows (step base)
    float bzall[3];                      // bz + source for this step

    // ---- init: m0 = (0,1,0); publish tagged ----
    mxr[1] = 0.0f; myr[1] = 1.0f; mzr[1] = 0.0f;
    PUBLISH_M();

    // ---- relax phase: alpha = 0.5, no source ----
    {
        const float alpha = 0.5f;
        const float inv = 1.0f / (1.0f + alpha * alpha);
        #pragma unroll
        for (int k = 0; k < 3; k++) bzall[k] = bzr[k];
        for (int s = 0; s < RELAXN; s++) {
            POLL_FILL_M();
            RK4STEP();
        }
    }
    const float mrx = mxr[1], mry = myr[1], mrz = mzr[1];   // m_relaxed (own)

    // ---- driven phase: alpha = 0.01 ----
    {
        const float alpha = 0.01f;
        const float inv = 1.0f / (1.0f + alpha * alpha);
        for (int sgn = 0; sgn < NSIG; sgn++) {
            if (sgn > 0) {   // reset to m_relaxed (tagged publish event)
                mxr[1] = mrx; myr[1] = mry; mzr[1] = mrz;
                PUBLISH_M();
            }
            for (int t = 0; t < TSTEPS; t++) {
                const float* sp = sig + (sgn * TSTEPS + t) * NSRC;
                float sv0 = __ldg(sp + 0), sv1 = __ldg(sp + 1), sv2 = __ldg(sp + 2);
                #pragma unroll
                for (int k = 0; k < 3; k++)
                    bzall[k] = bzr[k] + ((sid[k] == 0) ? sv0 :
                                         (sid[k] == 1) ? sv1 :
                                         (sid[k] == 2) ? sv2 : 0.0f);
                POLL_FILL_M();
                RK4STEP();
                if (pid >= 0) {
                    float val = final_board ? (mzr[1] - mrz) * Msat : mzr[1];
                    out[(sgn * TSTEPS + t) * NPROBE + pid] = val;
                }
            }
        }
    }

    // Persist tag bases for the next graph replay (own slot only).
    if (tid == 0) {
        g_base[8 * r]     = ms;
        g_base[8 * r + 1] = us;
    }
}

extern "C" void kernel_launch(void* const* d_in, const int* in_sizes, int n_in,
                              void* d_out, int out_size) {
    const float* sig    = (const float*)d_in[0];  // (2, 256, 3)
    const float* Bext   = (const float*)d_in[1];  // (1, 3, 256, 256)
    const float* MsatP  = (const float*)d_in[2];  // scalar
    const int*   srcP   = (const int*)d_in[3];    // (3, 2)
    const int*   probeP = (const int*)d_in[4];    // (5, 2)
    const int*   finalP = (const int*)d_in[5];    // scalar
    float* out = (float*)d_out;                   // (2, 256, 5)
    (void)in_sizes; (void)n_in; (void)out_size;

    cudaFuncSetAttribute(mm_kernel,
                         cudaFuncAttributeMaxDynamicSharedMemorySize,
                         SMEM_BYTES);
    mm_kernel<<<NBLK, NT, SMEM_BYTES>>>(sig, Bext, MsatP, srcP, probeP,
                                        finalP, out);
}